// round 8
// baseline (speedup 1.0000x reference)
#include <cuda_runtime.h>
#include <cstdint>

#define NN   4096
#define MMm  4096
#define DD   128
#define CC   4
#define NNZ  262144
#define KDIM 512
#define KADD 26214
#define NM   (NN * MMm)
#define CAPC (4u * 1024u * 1024u)

// GEMM tiling (mma.sync tf32 path)
#define MT      128
#define NT      128
#define KCH     32
#define NCHUNK  (KDIM / KCH)          // 16
#define LDK     36                    // padded k-stride in floats (32+4)
#define PLANE_F (128 * LDK)           // 4608 floats per plane
#define STAGE_F (4 * PLANE_F)         // 18432 floats per stage
#define SMEM_BYTES (2 * STAGE_F * 4)  // 147456 bytes
#define GT      512                   // gemm threads

// ---------------- scratch (static device memory; no allocs allowed) ----------------
__device__ int       g_cnt[MMm];             // segment counts
__device__ unsigned  g_eoff[MMm + 1];        // CSR offsets
__device__ unsigned  g_ecur[MMm];            // fill cursors
__device__ int       g_eidx[NNZ];            // CSR node indices
__device__ float     g_Ahi[NN * KDIM];       // node feature tf32 hi plane
__device__ float     g_Alo[NN * KDIM];       // node feature tf32 lo plane
__device__ float     g_Bhi[MMm * KDIM];      // edge feature tf32 hi plane
__device__ float     g_Blo[MMm * KDIM];      // edge feature tf32 lo plane
__device__ float     g_S[NM];                // similarity matrix (masked)
__device__ unsigned  g_hist[2048];
__device__ unsigned  g_cand[CAPC];
__device__ unsigned  g_candCount;
__device__ unsigned  g_B1;
__device__ unsigned  g_r1;
__device__ unsigned  g_Tbits;

__device__ __forceinline__ unsigned f2ord(float f) {
    unsigned u = __float_as_uint(f);
    return (u & 0x80000000u) ? ~u : (u | 0x80000000u);
}
__device__ __forceinline__ float tf32r(float x) {
    uint32_t o;
    asm("cvt.rna.tf32.f32 %0, %1;" : "=r"(o) : "f"(x));
    return __uint_as_float(o);
}
__device__ __forceinline__ void cpa16(uint32_t dst, const void* src) {
    asm volatile("cp.async.cg.shared.global [%0], [%1], 16;"
                 :: "r"(dst), "l"(__cvta_generic_to_global(src)) : "memory");
}
// m16n8k8 tf32 mma: D = A*B + D  (row.col), fp32 accumulate
__device__ __forceinline__ void mma8(float* c,
                                     uint32_t a0, uint32_t a1, uint32_t a2, uint32_t a3,
                                     uint32_t b0, uint32_t b1) {
    asm volatile(
        "mma.sync.aligned.m16n8k8.row.col.f32.tf32.tf32.f32 "
        "{%0,%1,%2,%3}, {%4,%5,%6,%7}, {%8,%9}, {%0,%1,%2,%3};"
        : "+f"(c[0]), "+f"(c[1]), "+f"(c[2]), "+f"(c[3])
        : "r"(a0), "r"(a1), "r"(a2), "r"(a3), "r"(b0), "r"(b1));
}

// ---------------- K0: zero transient state (runs every replay) ----------------
__global__ void k_zero() {
    int i  = blockIdx.x * blockDim.x + threadIdx.x;
    int st = gridDim.x * blockDim.x;
    for (int j = i; j < MMm;  j += st) { g_cnt[j] = 0; g_ecur[j] = 0; }
    for (int j = i; j < 2048; j += st) g_hist[j] = 0;
    if (i == 0) g_candCount = 0;
}

// ---------------- CSR build: count -> prefix -> fill ----------------
__global__ void k_count(const int* __restrict__ E) {
    int i = blockIdx.x * blockDim.x + threadIdx.x;
    if (i < NNZ) atomicAdd(&g_cnt[E[i]], 1);
}

__global__ void k_prefix() {   // exclusive prefix of g_cnt into g_eoff (1 block, 1024 thr)
    __shared__ unsigned s[1024];
    int t = threadIdx.x;
    unsigned c0 = g_cnt[4*t], c1 = g_cnt[4*t+1], c2 = g_cnt[4*t+2], c3 = g_cnt[4*t+3];
    s[t] = c0 + c1 + c2 + c3;
    __syncthreads();
    for (int off = 1; off < 1024; off <<= 1) {
        unsigned v = (t >= off) ? s[t - off] : 0u;
        __syncthreads();
        s[t] += v;
        __syncthreads();
    }
    unsigned base = t ? s[t-1] : 0u;
    g_eoff[4*t]   = base;
    g_eoff[4*t+1] = base + c0;
    g_eoff[4*t+2] = base + c0 + c1;
    g_eoff[4*t+3] = base + c0 + c1 + c2;
    if (t == 1023) g_eoff[MMm] = s[1023];
}

__global__ void k_fill(const int* __restrict__ V, const int* __restrict__ E) {
    int i = blockIdx.x * blockDim.x + threadIdx.x;
    if (i < NNZ) {
        int e = E[i];
        unsigned pos = atomicAdd(&g_ecur[e], 1u);
        g_eidx[g_eoff[e] + pos] = V[i];
    }
}

// ---------------- K2: build 0.5 * l2norm(x * w_c) features, tf32 hi/lo planes ----------------
// Edge branch gathers node rows via CSR (x4 unrolled; int64 adds are exact/associative).
__global__ void k_feat(const float* __restrict__ X, const float* __restrict__ W) {
    int r   = blockIdx.x;
    int isE = blockIdx.y;
    int d   = threadIdx.x;   // 128 threads
    __shared__ float red[128];
    float x;
    if (!isE) {
        x = X[(size_t)r * DD + d];
    } else {
        unsigned s0 = g_eoff[r], s1 = g_eoff[r + 1];
        long long a0 = 0, a1 = 0, a2 = 0, a3 = 0;
        unsigned j = s0;
        for (; j + 4 <= s1; j += 4) {
            int v0 = g_eidx[j], v1 = g_eidx[j+1], v2 = g_eidx[j+2], v3 = g_eidx[j+3];
            a0 += __double2ll_rn((double)X[(size_t)v0 * DD + d] * 4294967296.0);
            a1 += __double2ll_rn((double)X[(size_t)v1 * DD + d] * 4294967296.0);
            a2 += __double2ll_rn((double)X[(size_t)v2 * DD + d] * 4294967296.0);
            a3 += __double2ll_rn((double)X[(size_t)v3 * DD + d] * 4294967296.0);
        }
        for (; j < s1; j++)
            a0 += __double2ll_rn((double)X[(size_t)g_eidx[j] * DD + d] * 4294967296.0);
        long long acc = a0 + a1 + a2 + a3;
        float cnt = (float)(s1 - s0);
        float sum = (float)((double)acc * (1.0 / 4294967296.0));
        x = __fdiv_rn(sum, fmaxf(cnt, 1.0f));
    }
    float* dhi = isE ? g_Bhi : g_Ahi;
    float* dlo = isE ? g_Blo : g_Alo;
#pragma unroll
    for (int c = 0; c < CC; c++) {
        float v = x * W[c * DD + d];
        red[d] = v * v;
        __syncthreads();
        for (int s2 = 64; s2 > 0; s2 >>= 1) {
            if (d < s2) red[d] += red[d + s2];
            __syncthreads();
        }
        float nrm = __fsqrt_rn(red[0]);
        __syncthreads();
        float val = 0.5f * __fdiv_rn(v, fmaxf(nrm, 1e-12f));
        float hi = tf32r(val);
        float lo = tf32r(val - hi);
        dhi[(size_t)r * KDIM + c * DD + d] = hi;
        dlo[(size_t)r * KDIM + c * DD + d] = lo;
    }
}

// ---------------- K3: 3xTF32 mma.sync GEMM  S = A(4096x512) * B(4096x512)^T ----------------
// 128x128 CTA tile, 16 warps (4x4), warp tile 32x32, k-chunk 32, double-buffered cp.async.
__global__ void __launch_bounds__(GT, 1) k_gemm() {
    extern __shared__ __align__(128) float smf[];
    uint32_t sb;
    asm("{ .reg .u64 t; cvta.to.shared.u64 t, %1; cvt.u32.u64 %0, t; }"
        : "=r"(sb) : "l"(smf));
    const int tid = threadIdx.x;
    const int wid = tid >> 5, lane = tid & 31;
    const int g = lane >> 2, t = lane & 3;
    const int wm = wid >> 2, wn = wid & 3;
    const int bm = blockIdx.y * MT, bn = blockIdx.x * NT;

    float acc[2][4][4];
#pragma unroll
    for (int mt = 0; mt < 2; mt++)
#pragma unroll
        for (int nt = 0; nt < 4; nt++)
#pragma unroll
            for (int r = 0; r < 4; r++) acc[mt][nt][r] = 0.0f;

    // ---- chunk loader: 4 planes x 1024 float4 via cp.async (8 per thread) ----
    auto load_chunk = [&](int kt, int stage) {
        uint32_t base = sb + (uint32_t)stage * (STAGE_F * 4);
#pragma unroll
        for (int i = 0; i < 2; i++) {
            int idx = tid + i * GT;
            int row = idx >> 3, c4 = idx & 7;
            uint32_t so = (uint32_t)(row * (LDK * 4) + c4 * 16);
            size_t goA = (size_t)(bm + row) * KDIM + kt * KCH + c4 * 4;
            size_t goB = (size_t)(bn + row) * KDIM + kt * KCH + c4 * 4;
            cpa16(base + so,                  g_Ahi + goA);
            cpa16(base + PLANE_F * 4  + so,   g_Alo + goA);
            cpa16(base + PLANE_F * 8  + so,   g_Bhi + goB);
            cpa16(base + PLANE_F * 12 + so,   g_Blo + goB);
        }
        asm volatile("cp.async.commit_group;" ::: "memory");
    };

    load_chunk(0, 0);

    for (int kt = 0; kt < NCHUNK; kt++) {
        int buf = kt & 1;
        if (kt + 1 < NCHUNK) {
            load_chunk(kt + 1, buf ^ 1);
            asm volatile("cp.async.wait_group 1;" ::: "memory");
        } else {
            asm volatile("cp.async.wait_group 0;" ::: "memory");
        }
        __syncthreads();

        const float* st_ = smf + buf * STAGE_F;
        const float* Ah = st_;
        const float* Al = st_ + PLANE_F;
        const float* Bh = st_ + 2 * PLANE_F;
        const float* Bl = st_ + 3 * PLANE_F;

#pragma unroll
        for (int ks = 0; ks < 4; ks++) {
            const int kb = ks * 8;
            uint32_t bh[4][2], bl[4][2];
#pragma unroll
            for (int nt = 0; nt < 4; nt++) {
                int n0 = wn * 32 + nt * 8 + g;
                int o  = n0 * LDK + kb + t;
                bh[nt][0] = __float_as_uint(Bh[o]);
                bh[nt][1] = __float_as_uint(Bh[o + 4]);
                bl[nt][0] = __float_as_uint(Bl[o]);
                bl[nt][1] = __float_as_uint(Bl[o + 4]);
            }
#pragma unroll
            for (int mt = 0; mt < 2; mt++) {
                int r0 = wm * 32 + mt * 16 + g;
                int o0 = r0 * LDK + kb + t;
                int o1 = (r0 + 8) * LDK + kb + t;
                uint32_t ah0 = __float_as_uint(Ah[o0]);
                uint32_t ah1 = __float_as_uint(Ah[o1]);
                uint32_t ah2 = __float_as_uint(Ah[o0 + 4]);
                uint32_t ah3 = __float_as_uint(Ah[o1 + 4]);
                uint32_t al0 = __float_as_uint(Al[o0]);
                uint32_t al1 = __float_as_uint(Al[o1]);
                uint32_t al2 = __float_as_uint(Al[o0 + 4]);
                uint32_t al3 = __float_as_uint(Al[o1 + 4]);
#pragma unroll
                for (int nt = 0; nt < 4; nt++) {
                    mma8(acc[mt][nt], ah0, ah1, ah2, ah3, bh[nt][0], bh[nt][1]);
                    mma8(acc[mt][nt], ah0, ah1, ah2, ah3, bl[nt][0], bl[nt][1]);
                    mma8(acc[mt][nt], al0, al1, al2, al3, bh[nt][0], bh[nt][1]);
                }
            }
        }
        __syncthreads();
    }

    // ---- epilogue: c0:(g,2t) c1:(g,2t+1) c2:(g+8,2t) c3:(g+8,2t+1) ----
#pragma unroll
    for (int mt = 0; mt < 2; mt++) {
        int r0 = bm + wm * 32 + mt * 16 + g;
#pragma unroll
        for (int nt = 0; nt < 4; nt++) {
            int c = bn + wn * 32 + nt * 8 + 2 * t;
            *(float2*)(g_S + (size_t)r0 * MMm + c)       = make_float2(acc[mt][nt][0], acc[mt][nt][1]);
            *(float2*)(g_S + (size_t)(r0 + 8) * MMm + c) = make_float2(acc[mt][nt][2], acc[mt][nt][3]);
        }
    }
}

// ---------------- K4: mask existing incidences (dedup-safe) ----------------
__global__ void k_mask(const int* __restrict__ V, const int* __restrict__ E) {
    int i = blockIdx.x * blockDim.x + threadIdx.x;
    if (i < NNZ) {
        atomicExch(&g_S[(size_t)V[i] * MMm + E[i]], -1e30f);
    }
}

// ---------------- K5: top-11-bit histogram (warp match-aggregated) ----------------
__global__ void k_hist() {
    __shared__ unsigned h[2048];
    for (int j = threadIdx.x; j < 2048; j += blockDim.x) h[j] = 0;
    __syncthreads();
    int lane = threadIdx.x & 31;
    int i  = blockIdx.x * blockDim.x + threadIdx.x;
    int st = gridDim.x * blockDim.x;
    const float4* S4 = (const float4*)g_S;
    // NM/4 = 4194304 is an exact multiple of st (524288): all threads run 8 iterations.
    for (int j = i; j < NM / 4; j += st) {
        float4 s = S4[j];
        unsigned b[4] = { f2ord(s.x) >> 21, f2ord(s.y) >> 21,
                          f2ord(s.z) >> 21, f2ord(s.w) >> 21 };
#pragma unroll
        for (int q = 0; q < 4; q++) {
            unsigned m = __match_any_sync(0xFFFFFFFFu, b[q]);
            if ((int)(__ffs(m) - 1) == lane) atomicAdd(&h[b[q]], __popc(m));
        }
    }
    __syncthreads();
    for (int j = threadIdx.x; j < 2048; j += blockDim.x)
        if (h[j]) atomicAdd(&g_hist[j], h[j]);
}

// ---------------- K6: find threshold bucket (1 block, 1024 thr) ----------------
__global__ void k_pick() {
    __shared__ unsigned c[2048];
    int t = threadIdx.x;
    c[t] = g_hist[t];
    c[t + 1024] = g_hist[t + 1024];
    __syncthreads();
    for (int off = 1; off < 2048; off <<= 1) {
        unsigned a0 = (t + off < 2048) ? c[t + off] : 0u;
        unsigned a1 = (t + 1024 + off < 2048) ? c[t + 1024 + off] : 0u;
        __syncthreads();
        c[t] += a0; c[t + 1024] += a1;
        __syncthreads();
    }
    for (int b = t; b < 2048; b += 1024) {
        unsigned cum = c[b], nxt = (b + 1 < 2048) ? c[b + 1] : 0u;
        if (cum >= (unsigned)KADD && nxt < (unsigned)KADD) {
            g_B1 = (unsigned)b;
            g_r1 = (unsigned)KADD - nxt;
        }
    }
}

// ---------------- K7: collect candidates (ballot-aggregated counter) ----------------
__global__ void k_collect() {
    unsigned B1 = g_B1;
    int lane = threadIdx.x & 31;
    int i  = blockIdx.x * blockDim.x + threadIdx.x;
    int st = gridDim.x * blockDim.x;
    const float4* S4 = (const float4*)g_S;
    // uniform trip count (8) across all threads -> warp-synchronous ballots are safe
    for (int j = i; j < NM / 4; j += st) {
        float4 s = S4[j];
        unsigned u[4] = { f2ord(s.x), f2ord(s.y), f2ord(s.z), f2ord(s.w) };
#pragma unroll
        for (int q = 0; q < 4; q++) {
            bool pred = (u[q] >> 21) == B1;
            unsigned m = __ballot_sync(0xFFFFFFFFu, pred);
            if (m) {
                int leader = __ffs(m) - 1;
                unsigned base = 0;
                if (lane == leader) base = atomicAdd(&g_candCount, (unsigned)__popc(m));
                base = __shfl_sync(0xFFFFFFFFu, base, leader);
                unsigned rank = __popc(m & ((1u << lane) - 1u));
                if (pred && base + rank < CAPC) g_cand[base + rank] = u[q];
            }
        }
    }
}

// ---------------- K8: exact k-th value via 11+10 bit refine (1 block) ----------------
__global__ void k_select() {
    __shared__ unsigned h[2048];
    __shared__ unsigned sb2, sr2;
    int t = threadIdx.x;  // 1024
    unsigned nc = g_candCount; if (nc > CAPC) nc = CAPC;
    unsigned r1 = g_r1;

    h[t] = 0; h[t + 1024] = 0;
    __syncthreads();
    for (unsigned i = t; i < nc; i += 1024)
        atomicAdd(&h[(g_cand[i] >> 10) & 2047u], 1u);
    __syncthreads();
    for (int off = 1; off < 2048; off <<= 1) {
        unsigned a0 = (t + off < 2048) ? h[t + off] : 0u;
        unsigned a1 = (t + 1024 + off < 2048) ? h[t + 1024 + off] : 0u;
        __syncthreads();
        h[t] += a0; h[t + 1024] += a1;
        __syncthreads();
    }
    for (int b = t; b < 2048; b += 1024) {
        unsigned cum = h[b], nxt = (b + 1 < 2048) ? h[b + 1] : 0u;
        if (cum >= r1 && nxt < r1) { sb2 = (unsigned)b; sr2 = r1 - nxt; }
    }
    __syncthreads();
    unsigned b2 = sb2, r2 = sr2;

    h[t] = 0;
    __syncthreads();
    for (unsigned i = t; i < nc; i += 1024) {
        unsigned u = g_cand[i];
        if (((u >> 10) & 2047u) == b2) atomicAdd(&h[u & 1023u], 1u);
    }
    __syncthreads();
    for (int off = 1; off < 1024; off <<= 1) {
        unsigned a = (t + off < 1024) ? h[t + off] : 0u;
        __syncthreads();
        h[t] += a;
        __syncthreads();
    }
    unsigned cum = h[t], nxt = (t + 1 < 1024) ? h[t + 1] : 0u;
    if (cum >= r2 && nxt < r2)
        g_Tbits = (g_B1 << 21) | (b2 << 10) | (unsigned)t;
}

// ---------------- K9: fused output ----------------
__device__ __forceinline__ float outval(float h, float p, float e, float s, unsigned T) {
    float enr = h + ((f2ord(s) >= T) ? 1.0f : 0.0f);
    float pa = __fadd_rn(p, 1e-8f);
    float pb = __fadd_rn(__fsub_rn(1.0f, p), 1e-8f);
    float eb = __fsub_rn(1.0f, e);
    double lhs = (double)e  * (double)pa;
    double rhs = (double)eb * (double)pb;
    return (lhs > rhs) ? enr : 0.0f;
}

__global__ void k_final(const float* __restrict__ H, const float* __restrict__ P,
                        const float* __restrict__ Eps, float* __restrict__ out) {
    unsigned T = g_Tbits;
    int i  = blockIdx.x * blockDim.x + threadIdx.x;
    int st = gridDim.x * blockDim.x;
    const float4* H4 = (const float4*)H;
    const float4* P4 = (const float4*)P;
    const float4* E4 = (const float4*)Eps;
    const float4* S4 = (const float4*)g_S;
    float4* O4 = (float4*)out;
    for (int j = i; j < NM / 4; j += st) {
        float4 h4 = H4[j], p4 = P4[j], e4 = E4[j], s4 = S4[j];
        float4 o;
        o.x = outval(h4.x, p4.x, e4.x, s4.x, T);
        o.y = outval(h4.y, p4.y, e4.y, s4.y, T);
        o.z = outval(h4.z, p4.z, e4.z, s4.z, T);
        o.w = outval(h4.w, p4.w, e4.w, s4.w, T);
        O4[j] = o;
    }
}

// ---------------- launch ----------------
extern "C" void kernel_launch(void* const* d_in, const int* in_sizes, int n_in,
                              void* d_out, int out_size) {
    const float* X   = (const float*)d_in[0];
    const float* H   = (const float*)d_in[1];
    const int*   V   = (const int*)d_in[2];
    const int*   E   = (const int*)d_in[3];
    const float* P   = (const float*)d_in[4];
    const float* W   = (const float*)d_in[5];
    const float* Eps = (const float*)d_in[6];
    float* out = (float*)d_out;

    cudaFuncSetAttribute(k_gemm, cudaFuncAttributeMaxDynamicSharedMemorySize, SMEM_BYTES);

    k_zero<<<64, 256>>>();
    k_count<<<NNZ / 256, 256>>>(E);
    k_prefix<<<1, 1024>>>();
    k_fill<<<NNZ / 256, 256>>>(V, E);
    {
        dim3 fg(NN, 2);
        k_feat<<<fg, 128>>>(X, W);
    }
    {
        dim3 gg(MMm / NT, NN / MT);   // (32, 32)
        k_gemm<<<gg, GT, SMEM_BYTES>>>();
    }
    k_mask<<<NNZ / 256, 256>>>(V, E);
    k_hist<<<2048, 256>>>();
    k_pick<<<1, 1024>>>();
    k_collect<<<2048, 256>>>();
    k_select<<<1, 1024>>>();
    k_final<<<4096, 256>>>(H, P, Eps, out);
}

// round 9
// speedup vs baseline: 1.1265x; 1.1265x over previous
#include <cuda_runtime.h>
#include <cstdint>

#define NN   4096
#define MMm  4096
#define DD   128
#define CC   4
#define NNZ  262144
#define KDIM 512
#define KADD 26214
#define NM   (NN * MMm)
#define CAPC (4u * 1024u * 1024u)

// GEMM tiling (mma.sync tf32 path)
#define MT      128
#define NT      128
#define KCH     32
#define NCHUNK  (KDIM / KCH)          // 16
#define LDK     36                    // padded k-stride in floats (32+4)
#define PLANE_F (128 * LDK)           // 4608 floats per plane
#define STAGE_F (4 * PLANE_F)         // 18432 floats per stage
#define SMEM_BYTES (2 * STAGE_F * 4)  // 147456 bytes
#define GT      512                   // gemm threads

// ---------------- scratch (static device memory; no allocs allowed) ----------------
__device__ int       g_cnt[MMm];             // segment counts
__device__ unsigned  g_eoff[MMm + 1];        // CSR offsets
__device__ unsigned  g_ecur[MMm];            // fill cursors
__device__ int       g_eidx[NNZ];            // CSR node indices
__device__ float     g_Ahi[NN * KDIM];       // node feature tf32 hi plane
__device__ float     g_Alo[NN * KDIM];       // node feature tf32 lo plane
__device__ float     g_Bhi[MMm * KDIM];      // edge feature tf32 hi plane
__device__ float     g_Blo[MMm * KDIM];      // edge feature tf32 lo plane
__device__ float     g_S[NM];                // similarity matrix (masked)
__device__ unsigned char g_pk[NM / 4];       // packed (mask,H) bits: 2 bits/cell
__device__ unsigned  g_hist[2048];
__device__ unsigned  g_cand[CAPC];
__device__ unsigned  g_candCount;
__device__ unsigned  g_B1;
__device__ unsigned  g_r1;
__device__ unsigned  g_Tbits;

__device__ __forceinline__ unsigned f2ord(float f) {
    unsigned u = __float_as_uint(f);
    return (u & 0x80000000u) ? ~u : (u | 0x80000000u);
}
__device__ __forceinline__ float tf32r(float x) {
    uint32_t o;
    asm("cvt.rna.tf32.f32 %0, %1;" : "=r"(o) : "f"(x));
    return __uint_as_float(o);
}
__device__ __forceinline__ void cpa16(uint32_t dst, const void* src) {
    asm volatile("cp.async.cg.shared.global [%0], [%1], 16;"
                 :: "r"(dst), "l"(__cvta_generic_to_global(src)) : "memory");
}
// m16n8k8 tf32 mma: D = A*B + D  (row.col), fp32 accumulate
__device__ __forceinline__ void mma8(float* c,
                                     uint32_t a0, uint32_t a1, uint32_t a2, uint32_t a3,
                                     uint32_t b0, uint32_t b1) {
    asm volatile(
        "mma.sync.aligned.m16n8k8.row.col.f32.tf32.tf32.f32 "
        "{%0,%1,%2,%3}, {%4,%5,%6,%7}, {%8,%9}, {%0,%1,%2,%3};"
        : "+f"(c[0]), "+f"(c[1]), "+f"(c[2]), "+f"(c[3])
        : "r"(a0), "r"(a1), "r"(a2), "r"(a3), "r"(b0), "r"(b1));
}

// ---------------- K0: zero transient state (runs every replay) ----------------
__global__ void k_zero() {
    int i  = blockIdx.x * blockDim.x + threadIdx.x;
    int st = gridDim.x * blockDim.x;
    for (int j = i; j < MMm;  j += st) { g_cnt[j] = 0; g_ecur[j] = 0; }
    for (int j = i; j < 2048; j += st) g_hist[j] = 0;
    if (i == 0) g_candCount = 0;
}

// ---------------- K-pack: gumbel hard mask + H bit, 2 bits per cell (overlapped) ----------------
__device__ __forceinline__ unsigned pk1(float h, float p, float e) {
    float pa = __fadd_rn(p, 1e-8f);
    float pb = __fadd_rn(__fsub_rn(1.0f, p), 1e-8f);
    float eb = __fsub_rn(1.0f, e);
    unsigned m = ((double)e * (double)pa > (double)eb * (double)pb) ? 2u : 0u;
    return m | ((h != 0.0f) ? 1u : 0u);
}
__global__ void k_pack(const float* __restrict__ H, const float* __restrict__ P,
                       const float* __restrict__ Eps) {
    int j = blockIdx.x * blockDim.x + threadIdx.x;   // NM/4 threads
    const float4* H4 = (const float4*)H;
    const float4* P4 = (const float4*)P;
    const float4* E4 = (const float4*)Eps;
    float4 h = H4[j], p = P4[j], e = E4[j];
    unsigned b = pk1(h.x, p.x, e.x)
               | (pk1(h.y, p.y, e.y) << 2)
               | (pk1(h.z, p.z, e.z) << 4)
               | (pk1(h.w, p.w, e.w) << 6);
    g_pk[j] = (unsigned char)b;
}

// ---------------- CSR build: count -> prefix -> fill ----------------
__global__ void k_count(const int* __restrict__ E) {
    int i = blockIdx.x * blockDim.x + threadIdx.x;
    if (i < NNZ) atomicAdd(&g_cnt[E[i]], 1);
}

__global__ void k_prefix() {   // exclusive prefix of g_cnt into g_eoff (1 block, 1024 thr)
    __shared__ unsigned s[1024];
    int t = threadIdx.x;
    unsigned c0 = g_cnt[4*t], c1 = g_cnt[4*t+1], c2 = g_cnt[4*t+2], c3 = g_cnt[4*t+3];
    s[t] = c0 + c1 + c2 + c3;
    __syncthreads();
    for (int off = 1; off < 1024; off <<= 1) {
        unsigned v = (t >= off) ? s[t - off] : 0u;
        __syncthreads();
        s[t] += v;
        __syncthreads();
    }
    unsigned base = t ? s[t-1] : 0u;
    g_eoff[4*t]   = base;
    g_eoff[4*t+1] = base + c0;
    g_eoff[4*t+2] = base + c0 + c1;
    g_eoff[4*t+3] = base + c0 + c1 + c2;
    if (t == 1023) g_eoff[MMm] = s[1023];
}

__global__ void k_fill(const int* __restrict__ V, const int* __restrict__ E) {
    int i = blockIdx.x * blockDim.x + threadIdx.x;
    if (i < NNZ) {
        int e = E[i];
        unsigned pos = atomicAdd(&g_ecur[e], 1u);
        g_eidx[g_eoff[e] + pos] = V[i];
    }
}

// ---------------- K2: build 0.5 * l2norm(x * w_c) features, tf32 hi/lo planes ----------------
// Edge branch gathers node rows via CSR and does the deterministic fixed-point mean inline.
__global__ void k_feat(const float* __restrict__ X, const float* __restrict__ W) {
    int r   = blockIdx.x;
    int isE = blockIdx.y;
    int d   = threadIdx.x;   // 128 threads
    __shared__ float red[128];
    float x;
    if (!isE) {
        x = X[(size_t)r * DD + d];
    } else {
        unsigned s0 = g_eoff[r], s1 = g_eoff[r + 1];
        long long acc = 0;
        for (unsigned j = s0; j < s1; j++) {
            int v = g_eidx[j];
            acc += __double2ll_rn((double)X[(size_t)v * DD + d] * 4294967296.0);
        }
        float cnt = (float)(s1 - s0);
        float sum = (float)((double)acc * (1.0 / 4294967296.0));
        x = __fdiv_rn(sum, fmaxf(cnt, 1.0f));
    }
    float* dhi = isE ? g_Bhi : g_Ahi;
    float* dlo = isE ? g_Blo : g_Alo;
#pragma unroll
    for (int c = 0; c < CC; c++) {
        float v = x * W[c * DD + d];
        red[d] = v * v;
        __syncthreads();
        for (int s2 = 64; s2 > 0; s2 >>= 1) {
            if (d < s2) red[d] += red[d + s2];
            __syncthreads();
        }
        float nrm = __fsqrt_rn(red[0]);
        __syncthreads();
        float val = 0.5f * __fdiv_rn(v, fmaxf(nrm, 1e-12f));
        float hi = tf32r(val);
        float lo = tf32r(val - hi);
        dhi[(size_t)r * KDIM + c * DD + d] = hi;
        dlo[(size_t)r * KDIM + c * DD + d] = lo;
    }
}

// ---------------- K3: 3xTF32 mma.sync GEMM  S = A(4096x512) * B(4096x512)^T ----------------
// 128x128 CTA tile, 16 warps (4x4), warp tile 32x32, k-chunk 32, double-buffered cp.async.
__global__ void __launch_bounds__(GT, 1) k_gemm() {
    extern __shared__ __align__(128) float smf[];
    uint32_t sb;
    asm("{ .reg .u64 t; cvta.to.shared.u64 t, %1; cvt.u32.u64 %0, t; }"
        : "=r"(sb) : "l"(smf));
    const int tid = threadIdx.x;
    const int wid = tid >> 5, lane = tid & 31;
    const int g = lane >> 2, t = lane & 3;
    const int wm = wid >> 2, wn = wid & 3;
    const int bm = blockIdx.y * MT, bn = blockIdx.x * NT;

    float acc[2][4][4];
#pragma unroll
    for (int mt = 0; mt < 2; mt++)
#pragma unroll
        for (int nt = 0; nt < 4; nt++)
#pragma unroll
            for (int r = 0; r < 4; r++) acc[mt][nt][r] = 0.0f;

    // ---- chunk loader: 4 planes x 1024 float4 via cp.async (8 per thread) ----
    auto load_chunk = [&](int kt, int stage) {
        uint32_t base = sb + (uint32_t)stage * (STAGE_F * 4);
#pragma unroll
        for (int i = 0; i < 2; i++) {
            int idx = tid + i * GT;
            int row = idx >> 3, c4 = idx & 7;
            uint32_t so = (uint32_t)(row * (LDK * 4) + c4 * 16);
            size_t goA = (size_t)(bm + row) * KDIM + kt * KCH + c4 * 4;
            size_t goB = (size_t)(bn + row) * KDIM + kt * KCH + c4 * 4;
            cpa16(base + so,                  g_Ahi + goA);
            cpa16(base + PLANE_F * 4  + so,   g_Alo + goA);
            cpa16(base + PLANE_F * 8  + so,   g_Bhi + goB);
            cpa16(base + PLANE_F * 12 + so,   g_Blo + goB);
        }
        asm volatile("cp.async.commit_group;" ::: "memory");
    };

    load_chunk(0, 0);

    for (int kt = 0; kt < NCHUNK; kt++) {
        int buf = kt & 1;
        if (kt + 1 < NCHUNK) {
            load_chunk(kt + 1, buf ^ 1);
            asm volatile("cp.async.wait_group 1;" ::: "memory");
        } else {
            asm volatile("cp.async.wait_group 0;" ::: "memory");
        }
        __syncthreads();

        const float* st_ = smf + buf * STAGE_F;
        const float* Ah = st_;
        const float* Al = st_ + PLANE_F;
        const float* Bh = st_ + 2 * PLANE_F;
        const float* Bl = st_ + 3 * PLANE_F;

#pragma unroll
        for (int ks = 0; ks < 4; ks++) {
            const int kb = ks * 8;
            uint32_t bh[4][2], bl[4][2];
#pragma unroll
            for (int nt = 0; nt < 4; nt++) {
                int n0 = wn * 32 + nt * 8 + g;
                int o  = n0 * LDK + kb + t;
                bh[nt][0] = __float_as_uint(Bh[o]);
                bh[nt][1] = __float_as_uint(Bh[o + 4]);
                bl[nt][0] = __float_as_uint(Bl[o]);
                bl[nt][1] = __float_as_uint(Bl[o + 4]);
            }
#pragma unroll
            for (int mt = 0; mt < 2; mt++) {
                int r0 = wm * 32 + mt * 16 + g;
                int o0 = r0 * LDK + kb + t;
                int o1 = (r0 + 8) * LDK + kb + t;
                uint32_t ah0 = __float_as_uint(Ah[o0]);
                uint32_t ah1 = __float_as_uint(Ah[o1]);
                uint32_t ah2 = __float_as_uint(Ah[o0 + 4]);
                uint32_t ah3 = __float_as_uint(Ah[o1 + 4]);
                uint32_t al0 = __float_as_uint(Al[o0]);
                uint32_t al1 = __float_as_uint(Al[o1]);
                uint32_t al2 = __float_as_uint(Al[o0 + 4]);
                uint32_t al3 = __float_as_uint(Al[o1 + 4]);
#pragma unroll
                for (int nt = 0; nt < 4; nt++) {
                    mma8(acc[mt][nt], ah0, ah1, ah2, ah3, bh[nt][0], bh[nt][1]);
                    mma8(acc[mt][nt], ah0, ah1, ah2, ah3, bl[nt][0], bl[nt][1]);
                    mma8(acc[mt][nt], al0, al1, al2, al3, bh[nt][0], bh[nt][1]);
                }
            }
        }
        __syncthreads();
    }

    // ---- epilogue: c0:(g,2t) c1:(g,2t+1) c2:(g+8,2t) c3:(g+8,2t+1) ----
#pragma unroll
    for (int mt = 0; mt < 2; mt++) {
        int r0 = bm + wm * 32 + mt * 16 + g;
#pragma unroll
        for (int nt = 0; nt < 4; nt++) {
            int c = bn + wn * 32 + nt * 8 + 2 * t;
            *(float2*)(g_S + (size_t)r0 * MMm + c)       = make_float2(acc[mt][nt][0], acc[mt][nt][1]);
            *(float2*)(g_S + (size_t)(r0 + 8) * MMm + c) = make_float2(acc[mt][nt][2], acc[mt][nt][3]);
        }
    }
}

// ---------------- K4: mask existing incidences (dedup-safe) ----------------
__global__ void k_mask(const int* __restrict__ V, const int* __restrict__ E) {
    int i = blockIdx.x * blockDim.x + threadIdx.x;
    if (i < NNZ) {
        atomicExch(&g_S[(size_t)V[i] * MMm + E[i]], -1e30f);
    }
}

// ---------------- K5: top-11-bit histogram ----------------
__global__ void k_hist() {
    __shared__ unsigned h[2048];
    for (int j = threadIdx.x; j < 2048; j += blockDim.x) h[j] = 0;
    __syncthreads();
    int i  = blockIdx.x * blockDim.x + threadIdx.x;
    int st = gridDim.x * blockDim.x;
    const float4* S4 = (const float4*)g_S;
    for (int j = i; j < NM / 4; j += st) {
        float4 s = S4[j];
        atomicAdd(&h[f2ord(s.x) >> 21], 1u);
        atomicAdd(&h[f2ord(s.y) >> 21], 1u);
        atomicAdd(&h[f2ord(s.z) >> 21], 1u);
        atomicAdd(&h[f2ord(s.w) >> 21], 1u);
    }
    __syncthreads();
    for (int j = threadIdx.x; j < 2048; j += blockDim.x)
        if (h[j]) atomicAdd(&g_hist[j], h[j]);
}

// ---------------- K6: find threshold bucket (1 block, 1024 thr) ----------------
__global__ void k_pick() {
    __shared__ unsigned c[2048];
    int t = threadIdx.x;
    c[t] = g_hist[t];
    c[t + 1024] = g_hist[t + 1024];
    __syncthreads();
    for (int off = 1; off < 2048; off <<= 1) {
        unsigned a0 = (t + off < 2048) ? c[t + off] : 0u;
        unsigned a1 = (t + 1024 + off < 2048) ? c[t + 1024 + off] : 0u;
        __syncthreads();
        c[t] += a0; c[t + 1024] += a1;
        __syncthreads();
    }
    for (int b = t; b < 2048; b += 1024) {
        unsigned cum = c[b], nxt = (b + 1 < 2048) ? c[b + 1] : 0u;
        if (cum >= (unsigned)KADD && nxt < (unsigned)KADD) {
            g_B1 = (unsigned)b;
            g_r1 = (unsigned)KADD - nxt;
        }
    }
}

// ---------------- K7: collect candidates in threshold bucket ----------------
__global__ void k_collect() {
    unsigned B1 = g_B1;
    int i  = blockIdx.x * blockDim.x + threadIdx.x;
    int st = gridDim.x * blockDim.x;
    const float4* S4 = (const float4*)g_S;
    for (int j = i; j < NM / 4; j += st) {
        float4 s = S4[j];
        unsigned u0 = f2ord(s.x), u1 = f2ord(s.y), u2 = f2ord(s.z), u3 = f2ord(s.w);
        if ((u0 >> 21) == B1) { unsigned p = atomicAdd(&g_candCount, 1u); if (p < CAPC) g_cand[p] = u0; }
        if ((u1 >> 21) == B1) { unsigned p = atomicAdd(&g_candCount, 1u); if (p < CAPC) g_cand[p] = u1; }
        if ((u2 >> 21) == B1) { unsigned p = atomicAdd(&g_candCount, 1u); if (p < CAPC) g_cand[p] = u2; }
        if ((u3 >> 21) == B1) { unsigned p = atomicAdd(&g_candCount, 1u); if (p < CAPC) g_cand[p] = u3; }
    }
}

// ---------------- K8: exact k-th value via 11+10 bit refine (1 block) ----------------
__global__ void k_select() {
    __shared__ unsigned h[2048];
    __shared__ unsigned sb2, sr2;
    int t = threadIdx.x;  // 1024
    unsigned nc = g_candCount; if (nc > CAPC) nc = CAPC;
    unsigned r1 = g_r1;

    h[t] = 0; h[t + 1024] = 0;
    __syncthreads();
    for (unsigned i = t; i < nc; i += 1024)
        atomicAdd(&h[(g_cand[i] >> 10) & 2047u], 1u);
    __syncthreads();
    for (int off = 1; off < 2048; off <<= 1) {
        unsigned a0 = (t + off < 2048) ? h[t + off] : 0u;
        unsigned a1 = (t + 1024 + off < 2048) ? h[t + 1024 + off] : 0u;
        __syncthreads();
        h[t] += a0; h[t + 1024] += a1;
        __syncthreads();
    }
    for (int b = t; b < 2048; b += 1024) {
        unsigned cum = h[b], nxt = (b + 1 < 2048) ? h[b + 1] : 0u;
        if (cum >= r1 && nxt < r1) { sb2 = (unsigned)b; sr2 = r1 - nxt; }
    }
    __syncthreads();
    unsigned b2 = sb2, r2 = sr2;

    h[t] = 0;
    __syncthreads();
    for (unsigned i = t; i < nc; i += 1024) {
        unsigned u = g_cand[i];
        if (((u >> 10) & 2047u) == b2) atomicAdd(&h[u & 1023u], 1u);
    }
    __syncthreads();
    for (int off = 1; off < 1024; off <<= 1) {
        unsigned a = (t + off < 1024) ? h[t + off] : 0u;
        __syncthreads();
        h[t] += a;
        __syncthreads();
    }
    unsigned cum = h[t], nxt = (t + 1 < 1024) ? h[t + 1] : 0u;
    if (cum >= r2 && nxt < r2)
        g_Tbits = (g_B1 << 21) | (b2 << 10) | (unsigned)t;
}

// ---------------- K9: fused output (reads S + packed bits only) ----------------
__global__ void k_final(float* __restrict__ out) {
    unsigned T = g_Tbits;
    int i  = blockIdx.x * blockDim.x + threadIdx.x;
    int st = gridDim.x * blockDim.x;
    const float4* S4 = (const float4*)g_S;
    float4* O4 = (float4*)out;
    for (int j = i; j < NM / 4; j += st) {
        float4 s = S4[j];
        unsigned b = g_pk[j];
        float4 o;
        o.x = (b & 2u)   ? (float)((b & 1u)        + (f2ord(s.x) >= T)) : 0.0f;
        o.y = (b & 8u)   ? (float)(((b >> 2) & 1u) + (f2ord(s.y) >= T)) : 0.0f;
        o.z = (b & 32u)  ? (float)(((b >> 4) & 1u) + (f2ord(s.z) >= T)) : 0.0f;
        o.w = (b & 128u) ? (float)(((b >> 6) & 1u) + (f2ord(s.w) >= T)) : 0.0f;
        O4[j] = o;
    }
}

// ---------------- launch ----------------
extern "C" void kernel_launch(void* const* d_in, const int* in_sizes, int n_in,
                              void* d_out, int out_size) {
    const float* X   = (const float*)d_in[0];
    const float* H   = (const float*)d_in[1];
    const int*   V   = (const int*)d_in[2];
    const int*   E   = (const int*)d_in[3];
    const float* P   = (const float*)d_in[4];
    const float* W   = (const float*)d_in[5];
    const float* Eps = (const float*)d_in[6];
    float* out = (float*)d_out;

    static cudaStream_t s2 = nullptr;
    static cudaEvent_t evA = nullptr, evB = nullptr;
    if (!s2) {
        cudaStreamCreate(&s2);
        cudaEventCreateWithFlags(&evA, cudaEventDisableTiming);
        cudaEventCreateWithFlags(&evB, cudaEventDisableTiming);
    }

    cudaFuncSetAttribute(k_gemm, cudaFuncAttributeMaxDynamicSharedMemorySize, SMEM_BYTES);

    // fork: k_pack (reads only inputs) overlaps the whole CSR/feat/gemm phase
    cudaEventRecord(evA, 0);
    cudaStreamWaitEvent(s2, evA, 0);
    k_pack<<<NM / 4 / 256, 256, 0, s2>>>(H, P, Eps);
    cudaEventRecord(evB, s2);

    k_zero<<<64, 256>>>();
    k_count<<<NNZ / 256, 256>>>(E);
    k_prefix<<<1, 1024>>>();
    k_fill<<<NNZ / 256, 256>>>(V, E);
    {
        dim3 fg(NN, 2);
        k_feat<<<fg, 128>>>(X, W);
    }
    {
        dim3 gg(MMm / NT, NN / MT);   // (32, 32)
        k_gemm<<<gg, GT, SMEM_BYTES>>>();
    }
    k_mask<<<NNZ / 256, 256>>>(V, E);
    k_hist<<<2048, 256>>>();
    k_pick<<<1, 1024>>>();
    k_collect<<<2048, 256>>>();
    k_select<<<1, 1024>>>();

    // join: k_final needs g_pk
    cudaStreamWaitEvent(0, evB, 0);
    k_final<<<4096, 256>>>(out);
}